// round 14
// baseline (speedup 1.0000x reference)
#include <cuda_runtime.h>
#include <cuda_fp16.h>
#include <cstdint>

#define NBATCH 256
#define NSRC   512
#define NPRED  128
#define NDIM   512

// Scratch (device globals are the sanctioned alloc-free workaround).
static __device__ __align__(128) float  g_S[(size_t)NBATCH * NPRED * NSRC];     // 67 MB
static __device__ __align__(128) __half g_ench[(size_t)NBATCH * NSRC * NDIM];   // 134 MB
static __device__ __align__(128) __half g_encl[(size_t)NBATCH * NSRC * NDIM];   // 134 MB
static __device__ __align__(128) __half g_dech[(size_t)NBATCH * NPRED * NDIM];  // 33 MB
static __device__ __align__(128) __half g_decl[(size_t)NBATCH * NPRED * NDIM];  // 33 MB
static __device__ __align__(128) __half g_Wh[(size_t)NDIM * NDIM];
static __device__ __align__(128) __half g_Wl[(size_t)NDIM * NDIM];
static __device__ __align__(128) __half g_Qh[(size_t)NBATCH * NPRED * NDIM];    // 33 MB
static __device__ __align__(128) __half g_Ql[(size_t)NBATCH * NPRED * NDIM];    // 33 MB

// ---------------- helpers ----------------
__device__ __forceinline__ uint32_t saddr(const void* p) {
    return (uint32_t)__cvta_generic_to_shared(p);
}
__device__ __forceinline__ __half2 hi2(float a, float b) {
    return __halves2half2(__float2half_rn(a), __float2half_rn(b));
}
__device__ __forceinline__ __half2 lo2(float a, float b, __half2 h) {
    return __halves2half2(__float2half_rn(a - __half2float(__low2half(h))),
                          __float2half_rn(b - __half2float(__high2half(h))));
}
__device__ __forceinline__ uint32_t h2u(__half2 h) {
    return *reinterpret_cast<uint32_t*>(&h);
}
__device__ __forceinline__ void mma_f16(float (&d)[4], const uint32_t* a, const uint32_t* b) {
    asm volatile(
        "mma.sync.aligned.m16n8k16.row.col.f32.f16.f16.f32 "
        "{%0,%1,%2,%3}, {%4,%5,%6,%7}, {%8,%9}, {%0,%1,%2,%3};\n"
        : "+f"(d[0]), "+f"(d[1]), "+f"(d[2]), "+f"(d[3])
        : "r"(a[0]), "r"(a[1]), "r"(a[2]), "r"(a[3]), "r"(b[0]), "r"(b[1]));
}
__device__ __forceinline__ void ldsm4(uint32_t& r0, uint32_t& r1, uint32_t& r2, uint32_t& r3,
                                      uint32_t a) {
    asm volatile("ldmatrix.sync.aligned.m8n8.x4.shared.b16 {%0,%1,%2,%3}, [%4];"
                 : "=r"(r0), "=r"(r1), "=r"(r2), "=r"(r3) : "r"(a));
}
__device__ __forceinline__ void ldsm4t(uint32_t& r0, uint32_t& r1, uint32_t& r2, uint32_t& r3,
                                       uint32_t a) {
    asm volatile("ldmatrix.sync.aligned.m8n8.x4.trans.shared.b16 {%0,%1,%2,%3}, [%4];"
                 : "=r"(r0), "=r"(r1), "=r"(r2), "=r"(r3) : "r"(a));
}
__device__ __forceinline__ void cpa16(uint32_t dst, const void* src) {
    asm volatile("cp.async.ca.shared.global [%0], [%1], 16;" :: "r"(dst), "l"(src));
}
__device__ __forceinline__ void cp_commit() {
    asm volatile("cp.async.commit_group;" ::: "memory");
}
__device__ __forceinline__ void cp_wait1() {
    asm volatile("cp.async.wait_group 1;" ::: "memory");
}
__device__ __forceinline__ void cp_wait0() {
    asm volatile("cp.async.wait_group 0;" ::: "memory");
}
__device__ __forceinline__ void cvt_store(float4 v, __half* dh, __half* dl, size_t i4) {
    __half2 h0 = hi2(v.x, v.y), h1 = hi2(v.z, v.w);
    reinterpret_cast<uint2*>(dh)[i4] = make_uint2(h2u(h0), h2u(h1));
    reinterpret_cast<uint2*>(dl)[i4] =
        make_uint2(h2u(lo2(v.x, v.y, h0)), h2u(lo2(v.z, v.w, h1)));
}

// ============================================================================
// All-fp16 3-term split GEMM-NT: C(128x128 tile) = (Ah+Al) * (Bh+Bl)^T (lo*lo
// dropped). Inputs are preconverted fp16 h/l, row-major k-contiguous, caller
// pre-offset. 4 warps (2x2, 64x64 tiles), BK=32, cp.async double buffer.
// ============================================================================
#define BK     32
#define KPAD   40                     // halves/row; 20-word stride conflict-free
#define TILE_H (128 * KPAD)           // halves per matrix tile
#define SMEM_GEMM_BYTES (2 * 4 * TILE_H * 2)   // 81,920

template <bool WRITE_F16>
__device__ __forceinline__ void gemm_fp16_nt(const __half* __restrict__ Ahp,
                                             const __half* __restrict__ Alp,
                                             const __half* __restrict__ Bhp,
                                             const __half* __restrict__ Blp,
                                             float* __restrict__ Cf,
                                             __half* __restrict__ Ch,
                                             __half* __restrict__ Cl) {
    extern __shared__ __half sm[];

    const int tid  = threadIdx.x;        // 0..127
    const int lane = tid & 31;
    const int warp = tid >> 5;
    const int wm = (warp >> 1) << 6;
    const int wn = (warp & 1) << 6;
    const int g  = lane >> 2;
    const int tg = lane & 3;
    const int a_r = lane & 15;
    const int a_c = (lane >> 4) << 3;
    const int b_r = (lane & 7) + ((lane & 16) >> 1);
    const int b_c = lane & 8;

    const uint32_t smb = saddr(sm);

    // thread t loads row t: 4x 16B per matrix (= BK halves)
    auto load_chunk = [&](int c, int buf) {
        const uint32_t dbase = smb + (uint32_t)((buf * 4) * TILE_H + tid * KPAD) * 2;
        const size_t soff = (size_t)tid * 512 + c * BK;
        const __half* srcs[4] = {Ahp + soff, Alp + soff, Bhp + soff, Blp + soff};
#pragma unroll
        for (int m = 0; m < 4; m++) {
            uint32_t d = dbase + (uint32_t)(m * TILE_H * 2);
#pragma unroll
            for (int i = 0; i < 4; i++)
                cpa16(d + i * 16, (const char*)srcs[m] + i * 16);
        }
    };

    float acc[4][8][4];
#pragma unroll
    for (int i = 0; i < 4; i++)
#pragma unroll
        for (int j = 0; j < 8; j++)
#pragma unroll
            for (int r = 0; r < 4; r++) acc[i][j][r] = 0.0f;

    load_chunk(0, 0);
    cp_commit();
    load_chunk(1, 1);
    cp_commit();

    for (int c = 0; c < 16; c++) {
        const int cur = c & 1;
        if (c < 15) cp_wait1(); else cp_wait0();
        __syncthreads();

        const uint32_t ah_b = smb + (uint32_t)((cur * 4 + 0) * TILE_H) * 2;
        const uint32_t al_b = smb + (uint32_t)((cur * 4 + 1) * TILE_H) * 2;
        const uint32_t bh_b = smb + (uint32_t)((cur * 4 + 2) * TILE_H) * 2;
        const uint32_t bl_b = smb + (uint32_t)((cur * 4 + 3) * TILE_H) * 2;

#pragma unroll
        for (int kb = 0; kb < 32; kb += 16) {
            uint32_t bhf[4][4], blf[4][4];
#pragma unroll
            for (int jp = 0; jp < 4; jp++) {
                uint32_t off = (uint32_t)(((wn + jp * 16 + b_r) * KPAD + kb + b_c) << 1);
                ldsm4(bhf[jp][0], bhf[jp][1], bhf[jp][2], bhf[jp][3], bh_b + off);
                ldsm4(blf[jp][0], blf[jp][1], blf[jp][2], blf[jp][3], bl_b + off);
            }
#pragma unroll
            for (int i = 0; i < 4; i++) {
                uint32_t off = (uint32_t)(((wm + i * 16 + a_r) * KPAD + kb + a_c) << 1);
                uint32_t ah[4], al[4];
                ldsm4(ah[0], ah[1], ah[2], ah[3], ah_b + off);
                ldsm4(al[0], al[1], al[2], al[3], al_b + off);
                // term-major for acc dependency spacing
#pragma unroll
                for (int j = 0; j < 8; j++) {
                    uint32_t b2[2] = {bhf[j >> 1][(j & 1) << 1], bhf[j >> 1][((j & 1) << 1) + 1]};
                    mma_f16(acc[i][j], ah, b2);
                }
#pragma unroll
                for (int j = 0; j < 8; j++) {
                    uint32_t b2[2] = {blf[j >> 1][(j & 1) << 1], blf[j >> 1][((j & 1) << 1) + 1]};
                    mma_f16(acc[i][j], ah, b2);
                }
#pragma unroll
                for (int j = 0; j < 8; j++) {
                    uint32_t b2[2] = {bhf[j >> 1][(j & 1) << 1], bhf[j >> 1][((j & 1) << 1) + 1]};
                    mma_f16(acc[i][j], al, b2);
                }
            }
        }
        __syncthreads();
        if (c + 2 < 16) {
            load_chunk(c + 2, cur);
            cp_commit();
        }
    }

    // ---- epilogue ----
#pragma unroll
    for (int i = 0; i < 4; i++) {
        int r0 = wm + i * 16 + g;
#pragma unroll
        for (int j = 0; j < 8; j++) {
            int n0 = wn + j * 8 + (tg << 1);
            if (WRITE_F16) {
                __half2 h = hi2(acc[i][j][0], acc[i][j][1]);
                *reinterpret_cast<__half2*>(Ch + (size_t)r0 * 512 + n0) = h;
                *reinterpret_cast<__half2*>(Cl + (size_t)r0 * 512 + n0) =
                    lo2(acc[i][j][0], acc[i][j][1], h);
                h = hi2(acc[i][j][2], acc[i][j][3]);
                *reinterpret_cast<__half2*>(Ch + (size_t)(r0 + 8) * 512 + n0) = h;
                *reinterpret_cast<__half2*>(Cl + (size_t)(r0 + 8) * 512 + n0) =
                    lo2(acc[i][j][2], acc[i][j][3], h);
            } else {
                *reinterpret_cast<float2*>(Cf + (size_t)r0 * 512 + n0) =
                    make_float2(acc[i][j][0], acc[i][j][1]);
                *reinterpret_cast<float2*>(Cf + (size_t)(r0 + 8) * 512 + n0) =
                    make_float2(acc[i][j][2], acc[i][j][3]);
            }
        }
    }
}

// ---- convert dec + W to fp16 h/l (memory-bound; runs first) ----
__global__ __launch_bounds__(256) void k_cvt_dw(const float* __restrict__ dec,
                                                const float* __restrict__ W) {
    const size_t stride = (size_t)gridDim.x * 256;
    const size_t t0 = (size_t)blockIdx.x * 256 + threadIdx.x;
    const size_t nd4 = (size_t)NBATCH * NPRED * NDIM / 4;
    for (size_t i = t0; i < nd4; i += stride)
        cvt_store(reinterpret_cast<const float4*>(dec)[i], g_dech, g_decl, i);
    const size_t nw4 = (size_t)NDIM * NDIM / 4;
    for (size_t i = t0; i < nw4; i += stride)
        cvt_store(reinterpret_cast<const float4*>(W)[i], g_Wh, g_Wl, i);
}

// ---- Q GEMM (y==0) + enc conversion (y==1), overlapped in one launch ----
__global__ __launch_bounds__(128, 2) void k_query(const float* __restrict__ enc) {
    if (blockIdx.y == 1) {
        const size_t stride = (size_t)1024 * 128;
        const size_t t0 = ((size_t)blockIdx.z * 4 + blockIdx.x) * 128 + threadIdx.x;
        const size_t ne4 = (size_t)NBATCH * NSRC * NDIM / 4;
        for (size_t i = t0; i < ne4; i += stride)
            cvt_store(reinterpret_cast<const float4*>(enc)[i], g_ench, g_encl, i);
        return;
    }
    const size_t b = blockIdx.z;
    const size_t co = b * NPRED * NDIM + blockIdx.x * 128;
    gemm_fp16_nt<true>(g_dech + b * NPRED * NDIM, g_decl + b * NPRED * NDIM,
                       g_Wh + (size_t)blockIdx.x * 128 * 512,
                       g_Wl + (size_t)blockIdx.x * 128 * 512,
                       nullptr, g_Qh + co, g_Ql + co);
}

__global__ __launch_bounds__(128, 2) void k_scores() {
    const size_t b = blockIdx.z;
    const size_t eo = b * NSRC * NDIM + (size_t)blockIdx.x * 128 * 512;
    gemm_fp16_nt<false>(g_Qh + b * NPRED * NDIM, g_Ql + b * NPRED * NDIM,
                        g_ench + eo, g_encl + eo,
                        g_S + b * NPRED * NSRC + blockIdx.x * 128, nullptr, nullptr);
}

// ============================================================================
// Fused masked-softmax + context; Eh/El via cp.async from preconverted enc.
// ============================================================================
#define PSTR 520
#define ESTR 136

struct SmemCtx {
    __half P[64][PSTR];
    __half Eh[2][32][ESTR];
    __half El[2][32][ESTR];
};
#define SMEM_CTX_BYTES ((int)sizeof(SmemCtx))

__global__ __launch_bounds__(256, 2) void k_context(const int* __restrict__ mask,
                                                    float* __restrict__ out) {
    extern __shared__ char smem_raw[];
    SmemCtx* S = reinterpret_cast<SmemCtx*>(smem_raw);

    const size_t b = blockIdx.z;
    const int mhalf = blockIdx.y;
    const float* Sb = g_S + ((size_t)b * 128 + mhalf * 64) * 512;
    const size_t ebase = b * (size_t)NSRC * NDIM + blockIdx.x * 128;
    float* Cb = out + ((size_t)b * 128 + mhalf * 64) * 512 + blockIdx.x * 128;
    const int* mrow = mask + b * (size_t)NSRC;

    const int tid  = threadIdx.x;
    const int lane = tid & 31;
    const int warp = tid >> 5;
    const int wm = (warp >> 2) << 5;
    const int wn = (warp & 3) << 5;
    const int g  = lane >> 2;
    const int tg = lane & 3;

    const int a_r = lane & 15;
    const int a_c = (lane >> 4) << 3;
    const int bt_r = (lane & 7) + (lane & 8);
    const int bt_c = (lane >> 4) << 3;

    // cp.async mapping: row = tid>>3 (0..31), segs (tid&7) and (tid&7)+8 of 16B
    const int erow = tid >> 3;
    const int eseg = tid & 7;

    auto load_e = [&](int t, int bf) {
        const size_t src0 = (size_t)(t * 32 + erow) * 512 + ebase;
#pragma unroll
        for (int u = 0; u < 2; u++) {
            int s = eseg + u * 8;
            cpa16(saddr(&S->Eh[bf][erow][s * 8]), g_ench + src0 + s * 8);
            cpa16(saddr(&S->El[bf][erow][s * 8]), g_encl + src0 + s * 8);
        }
    };

    float acc[2][4][4];
#pragma unroll
    for (int i = 0; i < 2; i++)
#pragma unroll
        for (int j = 0; j < 4; j++)
#pragma unroll
            for (int r = 0; r < 4; r++) acc[i][j][r] = 0.0f;

    load_e(0, 0);
    cp_commit();
    load_e(1, 1);
    cp_commit();

    // ---- masked softmax prologue: 8 rows per warp -> resident fp16 P ----
    uint32_t mbits = 0;
#pragma unroll
    for (int i = 0; i < 4; i++) {
        int4 mk = *reinterpret_cast<const int4*>(mrow + i * 128 + lane * 4);
        mbits |= (uint32_t)((mk.x ? 1 : 0) | (mk.y ? 2 : 0) | (mk.z ? 4 : 0) | (mk.w ? 8 : 0))
                 << (i * 4);
    }
    for (int rr = 0; rr < 8; rr++) {
        int r = warp * 8 + rr;
        const float* row = Sb + (size_t)r * 512;
        float v[16];
        float m = -1e30f;
#pragma unroll
        for (int i = 0; i < 4; i++) {
            float4 x = *reinterpret_cast<const float4*>(row + i * 128 + lane * 4);
            v[i * 4 + 0] = (mbits >> (i * 4 + 0)) & 1 ? -1e30f : x.x;
            v[i * 4 + 1] = (mbits >> (i * 4 + 1)) & 1 ? -1e30f : x.y;
            v[i * 4 + 2] = (mbits >> (i * 4 + 2)) & 1 ? -1e30f : x.z;
            v[i * 4 + 3] = (mbits >> (i * 4 + 3)) & 1 ? -1e30f : x.w;
            m = fmaxf(m, fmaxf(fmaxf(v[i * 4], v[i * 4 + 1]), fmaxf(v[i * 4 + 2], v[i * 4 + 3])));
        }
#pragma unroll
        for (int o = 16; o; o >>= 1) m = fmaxf(m, __shfl_xor_sync(0xffffffffu, m, o));
        float sum = 0.0f;
#pragma unroll
        for (int i = 0; i < 16; i++) { v[i] = __expf(v[i] - m); sum += v[i]; }
#pragma unroll
        for (int o = 16; o; o >>= 1) sum += __shfl_xor_sync(0xffffffffu, sum, o);
        float inv = 1.0f / sum;
#pragma unroll
        for (int i = 0; i < 4; i++) {
            __half2 p0 = hi2(v[i * 4 + 0] * inv, v[i * 4 + 1] * inv);
            __half2 p1 = hi2(v[i * 4 + 2] * inv, v[i * 4 + 3] * inv);
            *reinterpret_cast<uint2*>(&S->P[r][i * 128 + lane * 4]) = make_uint2(h2u(p0), h2u(p1));
        }
    }

    const uint32_t p_b = saddr(&S->P[0][0]);

    for (int itr = 0; itr < 16; itr++) {
        const int cur = itr & 1;
        if (itr < 15) cp_wait1(); else cp_wait0();
        __syncthreads();

        const uint32_t eh_b = saddr(&S->Eh[cur][0][0]);
        const uint32_t el_b = saddr(&S->El[cur][0][0]);

#pragma unroll
        for (int s = 0; s < 2; s++) {
            const int kb = s * 16;
            uint32_t bh[2][4], bl[2][4];
#pragma unroll
            for (int jp = 0; jp < 2; jp++) {
                uint32_t off = (uint32_t)(((kb + bt_r) * ESTR + wn + jp * 16 + bt_c) << 1);
                ldsm4t(bh[jp][0], bh[jp][1], bh[jp][2], bh[jp][3], eh_b + off);
                ldsm4t(bl[jp][0], bl[jp][1], bl[jp][2], bl[jp][3], el_b + off);
            }
#pragma unroll
            for (int i = 0; i < 2; i++) {
                uint32_t off = (uint32_t)(((wm + i * 16 + a_r) * PSTR + itr * 32 + kb + a_c) << 1);
                uint32_t ap[4];
                ldsm4(ap[0], ap[1], ap[2], ap[3], p_b + off);
#pragma unroll
                for (int j = 0; j < 4; j++) {
                    uint32_t b2h[2] = {bh[j >> 1][(j & 1) << 1], bh[j >> 1][((j & 1) << 1) + 1]};
                    uint32_t b2l[2] = {bl[j >> 1][(j & 1) << 1], bl[j >> 1][((j & 1) << 1) + 1]};
                    mma_f16(acc[i][j], ap, b2h);
                    mma_f16(acc[i][j], ap, b2l);
                }
            }
        }
        __syncthreads();
        if (itr + 2 < 16) {
            load_e(itr + 2, cur);
            cp_commit();
        }
    }

#pragma unroll
    for (int i = 0; i < 2; i++) {
        int r0 = wm + i * 16 + g;
#pragma unroll
        for (int j = 0; j < 4; j++) {
            int n0 = wn + j * 8 + (tg << 1);
            *reinterpret_cast<float2*>(Cb + (size_t)r0 * 512 + n0) =
                make_float2(acc[i][j][0], acc[i][j][1]);
            *reinterpret_cast<float2*>(Cb + (size_t)(r0 + 8) * 512 + n0) =
                make_float2(acc[i][j][2], acc[i][j][3]);
        }
    }
}

extern "C" void kernel_launch(void* const* d_in, const int* in_sizes, int n_in,
                              void* d_out, int out_size) {
    const float* enc = nullptr;
    const float* dec = nullptr;
    const float* W = nullptr;
    const int* mask = nullptr;
    for (int i = 0; i < n_in; i++) {
        int n = in_sizes[i];
        if (n == NBATCH * NSRC * NDIM)        enc  = (const float*)d_in[i];
        else if (n == NBATCH * NPRED * NDIM)  dec  = (const float*)d_in[i];
        else if (n == NDIM * NDIM)            W    = (const float*)d_in[i];
        else if (n == NBATCH * NSRC)          mask = (const int*)d_in[i];
    }
    float* out = (float*)d_out;

    cudaFuncSetAttribute(k_query, cudaFuncAttributeMaxDynamicSharedMemorySize, SMEM_GEMM_BYTES);
    cudaFuncSetAttribute(k_scores, cudaFuncAttributeMaxDynamicSharedMemorySize, SMEM_GEMM_BYTES);
    cudaFuncSetAttribute(k_context, cudaFuncAttributeMaxDynamicSharedMemorySize, SMEM_CTX_BYTES);

    k_cvt_dw<<<512, 256>>>(dec, W);
    k_query<<<dim3(4, 2, NBATCH), 128, SMEM_GEMM_BYTES>>>(enc);
    k_scores<<<dim3(4, 1, NBATCH), 128, SMEM_GEMM_BYTES>>>();
    k_context<<<dim3(4, 2, NBATCH), 256, SMEM_CTX_BYTES>>>(mask, out);
}

// round 15
// speedup vs baseline: 1.2711x; 1.2711x over previous
#include <cuda_runtime.h>
#include <cuda_fp16.h>
#include <cstdint>

#define NBATCH 256
#define NSRC   512
#define NPRED  128
#define NDIM   512

// Scratch (device globals are the sanctioned alloc-free workaround).
static __device__ __align__(128) float  g_S[(size_t)NBATCH * NPRED * NSRC];    // 67 MB
static __device__ __align__(128) __half g_Wh[(size_t)NDIM * NDIM];             // 0.5 MB
static __device__ __align__(128) __half g_Wl[(size_t)NDIM * NDIM];             // 0.5 MB
static __device__ __align__(128) __half g_Qh[(size_t)NBATCH * NPRED * NDIM];   // 33 MB
static __device__ __align__(128) __half g_Ql[(size_t)NBATCH * NPRED * NDIM];   // 33 MB

// ---------------- helpers ----------------
__device__ __forceinline__ uint32_t saddr(const void* p) {
    return (uint32_t)__cvta_generic_to_shared(p);
}
__device__ __forceinline__ __half2 hi2(float a, float b) {
    return __halves2half2(__float2half_rn(a), __float2half_rn(b));
}
__device__ __forceinline__ __half2 lo2(float a, float b, __half2 h) {
    return __halves2half2(__float2half_rn(a - __half2float(__low2half(h))),
                          __float2half_rn(b - __half2float(__high2half(h))));
}
__device__ __forceinline__ uint32_t h2u(__half2 h) {
    return *reinterpret_cast<uint32_t*>(&h);
}
__device__ __forceinline__ void mma_f16(float (&d)[4], const uint32_t* a, const uint32_t* b) {
    asm volatile(
        "mma.sync.aligned.m16n8k16.row.col.f32.f16.f16.f32 "
        "{%0,%1,%2,%3}, {%4,%5,%6,%7}, {%8,%9}, {%0,%1,%2,%3};\n"
        : "+f"(d[0]), "+f"(d[1]), "+f"(d[2]), "+f"(d[3])
        : "r"(a[0]), "r"(a[1]), "r"(a[2]), "r"(a[3]), "r"(b[0]), "r"(b[1]));
}
__device__ __forceinline__ void ldsm4(uint32_t& r0, uint32_t& r1, uint32_t& r2, uint32_t& r3,
                                      uint32_t a) {
    asm volatile("ldmatrix.sync.aligned.m8n8.x4.shared.b16 {%0,%1,%2,%3}, [%4];"
                 : "=r"(r0), "=r"(r1), "=r"(r2), "=r"(r3) : "r"(a));
}
__device__ __forceinline__ void ldsm4t(uint32_t& r0, uint32_t& r1, uint32_t& r2, uint32_t& r3,
                                       uint32_t a) {
    asm volatile("ldmatrix.sync.aligned.m8n8.x4.trans.shared.b16 {%0,%1,%2,%3}, [%4];"
                 : "=r"(r0), "=r"(r1), "=r"(r2), "=r"(r3) : "r"(a));
}
__device__ __forceinline__ void cvt_store(float4 v, __half* dh, __half* dl, size_t i4) {
    __half2 h0 = hi2(v.x, v.y), h1 = hi2(v.z, v.w);
    reinterpret_cast<uint2*>(dh)[i4] = make_uint2(h2u(h0), h2u(h1));
    reinterpret_cast<uint2*>(dl)[i4] =
        make_uint2(h2u(lo2(v.x, v.y, h0)), h2u(lo2(v.z, v.w, h1)));
}

// ============================================================================
// fp16 hi/lo 3-term split GEMM-NT: C(128x128 tile) = (Ah+Al) * (Bh+Bl)^T.
// Structure identical to R13 (known 508us); per-operand source is either f32
// (converted in the staging store, as R13) or preconverted fp16 h/l (no cvt).
// 4 warps (2x2 grid, 64x64 warp tiles), BK=16, staged global loads.
// ============================================================================
#define KPAD 24  // halves per row; word = 12*row + c -> rows 0..7 hit distinct banks

template <bool A16, bool B16, bool OUT16>
__device__ __forceinline__ void split_gemm_nt(
    const float* __restrict__ Af, const __half* __restrict__ Ahg, const __half* __restrict__ Alg,
    const float* __restrict__ Bf, const __half* __restrict__ Bhg, const __half* __restrict__ Blg,
    float* __restrict__ Cf, __half* __restrict__ Ch, __half* __restrict__ Cl) {
    __shared__ __half Ah[128][KPAD], Al[128][KPAD];
    __shared__ __half Bh[128][KPAD], Bl[128][KPAD];

    const int tid  = threadIdx.x;        // 0..127
    const int lane = tid & 31;
    const int warp = tid >> 5;           // 0..3
    const int wm = (warp >> 1) << 6;     // 0 or 64
    const int wn = (warp & 1) << 6;      // 0 or 64
    const int g  = lane >> 2;
    const int tg = lane & 3;

    const int a_r = lane & 15;
    const int a_c = (lane >> 4) << 3;
    const int b_r = (lane & 7) + ((lane & 16) >> 1);
    const int b_c = lane & 8;

    const uint32_t ah_b = saddr(&Ah[0][0]);
    const uint32_t al_b = saddr(&Al[0][0]);
    const uint32_t bh_b = saddr(&Bh[0][0]);
    const uint32_t bl_b = saddr(&Bl[0][0]);

    // global loads: 4 lanes per row (64B contiguous f32 / 32B fp16), rows grow+32i
    const int grow = tid >> 2;           // 0..31
    const int gcol = (tid & 3) << 2;     // 0,4,8,12

    float acc[4][8][4];
#pragma unroll
    for (int i = 0; i < 4; i++)
#pragma unroll
        for (int j = 0; j < 8; j++)
#pragma unroll
            for (int r = 0; r < 4; r++) acc[i][j][r] = 0.0f;

    float4 sa[4], sb[4];
    uint2 sah[4], sal[4], sbh[4], sbl[4];

    auto lds_g = [&](int k0) {
#pragma unroll
        for (int i = 0; i < 4; i++) {
            const size_t off = (size_t)(grow + 32 * i) * 512 + k0 + gcol;
            if (A16) {
                sah[i] = *reinterpret_cast<const uint2*>(Ahg + off);
                sal[i] = *reinterpret_cast<const uint2*>(Alg + off);
            } else {
                sa[i] = *reinterpret_cast<const float4*>(Af + off);
            }
            if (B16) {
                sbh[i] = *reinterpret_cast<const uint2*>(Bhg + off);
                sbl[i] = *reinterpret_cast<const uint2*>(Blg + off);
            } else {
                sb[i] = *reinterpret_cast<const float4*>(Bf + off);
            }
        }
    };
    auto sts = [&]() {
#pragma unroll
        for (int i = 0; i < 4; i++) {
            int row = grow + 32 * i;
            if (A16) {
                *reinterpret_cast<uint2*>(&Ah[row][gcol]) = sah[i];
                *reinterpret_cast<uint2*>(&Al[row][gcol]) = sal[i];
            } else {
                float4 v = sa[i];
                __half2 h0 = hi2(v.x, v.y), h1 = hi2(v.z, v.w);
                *reinterpret_cast<uint2*>(&Ah[row][gcol]) = make_uint2(h2u(h0), h2u(h1));
                *reinterpret_cast<uint2*>(&Al[row][gcol]) =
                    make_uint2(h2u(lo2(v.x, v.y, h0)), h2u(lo2(v.z, v.w, h1)));
            }
            if (B16) {
                *reinterpret_cast<uint2*>(&Bh[row][gcol]) = sbh[i];
                *reinterpret_cast<uint2*>(&Bl[row][gcol]) = sbl[i];
            } else {
                float4 v = sb[i];
                __half2 h0 = hi2(v.x, v.y), h1 = hi2(v.z, v.w);
                *reinterpret_cast<uint2*>(&Bh[row][gcol]) = make_uint2(h2u(h0), h2u(h1));
                *reinterpret_cast<uint2*>(&Bl[row][gcol]) =
                    make_uint2(h2u(lo2(v.x, v.y, h0)), h2u(lo2(v.z, v.w, h1)));
            }
        }
    };

    lds_g(0);
    sts();
    __syncthreads();

    for (int itr = 0; itr < 32; itr++) {
        if (itr < 31) lds_g((itr + 1) * 16);  // overlaps compute below

        uint32_t bhf[4][4], blf[4][4];
#pragma unroll
        for (int jp = 0; jp < 4; jp++) {
            uint32_t off = (uint32_t)(((wn + jp * 16 + b_r) * KPAD + b_c) << 1);
            ldsm4(bhf[jp][0], bhf[jp][1], bhf[jp][2], bhf[jp][3], bh_b + off);
            ldsm4(blf[jp][0], blf[jp][1], blf[jp][2], blf[jp][3], bl_b + off);
        }
#pragma unroll
        for (int i = 0; i < 4; i++) {
            uint32_t off = (uint32_t)(((wm + i * 16 + a_r) * KPAD + a_c) << 1);
            uint32_t ah[4], al[4];
            ldsm4(ah[0], ah[1], ah[2], ah[3], ah_b + off);
            ldsm4(al[0], al[1], al[2], al[3], al_b + off);
#pragma unroll
            for (int j = 0; j < 8; j++) {
                uint32_t b2h[2] = {bhf[j >> 1][(j & 1) << 1], bhf[j >> 1][((j & 1) << 1) + 1]};
                uint32_t b2l[2] = {blf[j >> 1][(j & 1) << 1], blf[j >> 1][((j & 1) << 1) + 1]};
                mma_f16(acc[i][j], ah, b2h);
                mma_f16(acc[i][j], ah, b2l);
                mma_f16(acc[i][j], al, b2h);
            }
        }
        __syncthreads();
        if (itr < 31) {
            sts();
            __syncthreads();
        }
    }

    // ---- epilogue ----
#pragma unroll
    for (int i = 0; i < 4; i++) {
        int r0 = wm + i * 16 + g;
#pragma unroll
        for (int j = 0; j < 8; j++) {
            int n0 = wn + j * 8 + (tg << 1);
            if (OUT16) {
                __half2 h = hi2(acc[i][j][0], acc[i][j][1]);
                *reinterpret_cast<__half2*>(Ch + (size_t)r0 * 512 + n0) = h;
                *reinterpret_cast<__half2*>(Cl + (size_t)r0 * 512 + n0) =
                    lo2(acc[i][j][0], acc[i][j][1], h);
                h = hi2(acc[i][j][2], acc[i][j][3]);
                *reinterpret_cast<__half2*>(Ch + (size_t)(r0 + 8) * 512 + n0) = h;
                *reinterpret_cast<__half2*>(Cl + (size_t)(r0 + 8) * 512 + n0) =
                    lo2(acc[i][j][2], acc[i][j][3], h);
            } else {
                *reinterpret_cast<float2*>(Cf + (size_t)r0 * 512 + n0) =
                    make_float2(acc[i][j][0], acc[i][j][1]);
                *reinterpret_cast<float2*>(Cf + (size_t)(r0 + 8) * 512 + n0) =
                    make_float2(acc[i][j][2], acc[i][j][3]);
            }
        }
    }
}

// ---- tiny: W -> Wh/Wl (2 MB total traffic) ----
__global__ __launch_bounds__(256) void k_cvt_w(const float* __restrict__ W) {
    const size_t n4 = (size_t)NDIM * NDIM / 4;
    for (size_t i = (size_t)blockIdx.x * 256 + threadIdx.x; i < n4;
         i += (size_t)gridDim.x * 256)
        cvt_store(reinterpret_cast<const float4*>(W)[i], g_Wh, g_Wl, i);
}

// Q[b] = dec[b] @ W^T : A = dec f32 (in-loop cvt), B = Wh/Wl fp16, out = Qh/Ql fp16
__global__ __launch_bounds__(128, 2) void k_query(const float* __restrict__ dec) {
    const size_t b = blockIdx.z;
    const size_t wo = (size_t)blockIdx.x * 128 * 512;
    const size_t qo = b * NPRED * NDIM + blockIdx.x * 128;
    split_gemm_nt<false, true, true>(dec + b * NPRED * NDIM, nullptr, nullptr,
                                     nullptr, g_Wh + wo, g_Wl + wo,
                                     nullptr, g_Qh + qo, g_Ql + qo);
}

// S[b] = Q[b] @ enc[b]^T : A = Qh/Ql fp16, B = enc f32 (in-loop cvt), out = f32
__global__ __launch_bounds__(128, 2) void k_scores(const float* __restrict__ enc) {
    const size_t b = blockIdx.z;
    const size_t eo = b * (size_t)NSRC * NDIM + (size_t)blockIdx.x * 128 * 512;
    split_gemm_nt<true, false, false>(nullptr, g_Qh + b * NPRED * NDIM, g_Ql + b * NPRED * NDIM,
                                      enc + eo, nullptr, nullptr,
                                      g_S + b * NPRED * NSRC + blockIdx.x * 128,
                                      nullptr, nullptr);
}

// ============================================================================
// Fused masked-softmax + context (R13 verbatim, known good).
// ============================================================================
#define PSTR 520
#define ESTR 136

struct SmemCtx {
    __half P[64][PSTR];
    __half Eh[2][32][ESTR];
    __half El[2][32][ESTR];
};
#define SMEM_CTX_BYTES ((int)sizeof(SmemCtx))

__global__ __launch_bounds__(256, 2) void k_context(const float* __restrict__ enc,
                                                    const int* __restrict__ mask,
                                                    float* __restrict__ out) {
    extern __shared__ char smem_raw[];
    SmemCtx* S = reinterpret_cast<SmemCtx*>(smem_raw);

    const size_t b = blockIdx.z;
    const int mhalf = blockIdx.y;
    const float* Sb = g_S + ((size_t)b * 128 + mhalf * 64) * 512;
    const float* Bb = enc + b * (size_t)NSRC * NDIM + blockIdx.x * 128;
    float* Cb = out + ((size_t)b * 128 + mhalf * 64) * 512 + blockIdx.x * 128;
    const int* mrow = mask + b * (size_t)NSRC;

    const int tid  = threadIdx.x;
    const int lane = tid & 31;
    const int warp = tid >> 5;
    const int wm = (warp >> 2) << 5;
    const int wn = (warp & 3) << 5;
    const int g  = lane >> 2;
    const int tg = lane & 3;

    const int a_r = lane & 15;
    const int a_c = (lane >> 4) << 3;
    const int bt_r = (lane & 7) + (lane & 8);
    const int bt_c = (lane >> 4) << 3;

    const int brow = tid >> 3;
    const int bn0  = (tid & 7) << 4;

    float acc[2][4][4];
#pragma unroll
    for (int i = 0; i < 2; i++)
#pragma unroll
        for (int j = 0; j < 4; j++)
#pragma unroll
            for (int r = 0; r < 4; r++) acc[i][j][r] = 0.0f;

    float4 sbv[4];
    auto do_loads = [&](int t) {
        int k0 = t * 32;
#pragma unroll
        for (int it = 0; it < 4; it++)
            sbv[it] = *reinterpret_cast<const float4*>(Bb + (size_t)(k0 + brow) * 512 + bn0 + it * 4);
    };
    auto do_store = [&](int bf) {
#pragma unroll
        for (int u = 0; u < 2; u++) {
            int nn = bn0 + u * 8;
            float4 v0 = sbv[2 * u], v1 = sbv[2 * u + 1];
            __half2 h0 = hi2(v0.x, v0.y), h1 = hi2(v0.z, v0.w);
            __half2 h2 = hi2(v1.x, v1.y), h3 = hi2(v1.z, v1.w);
            *reinterpret_cast<uint4*>(&S->Eh[bf][brow][nn]) =
                make_uint4(h2u(h0), h2u(h1), h2u(h2), h2u(h3));
            *reinterpret_cast<uint4*>(&S->El[bf][brow][nn]) =
                make_uint4(h2u(lo2(v0.x, v0.y, h0)), h2u(lo2(v0.z, v0.w, h1)),
                           h2u(lo2(v1.x, v1.y, h2)), h2u(lo2(v1.z, v1.w, h3)));
        }
    };

    do_loads(0);

    uint32_t mbits = 0;
#pragma unroll
    for (int i = 0; i < 4; i++) {
        int4 mk = *reinterpret_cast<const int4*>(mrow + i * 128 + lane * 4);
        mbits |= (uint32_t)((mk.x ? 1 : 0) | (mk.y ? 2 : 0) | (mk.z ? 4 : 0) | (mk.w ? 8 : 0))
                 << (i * 4);
    }
    for (int rr = 0; rr < 8; rr++) {
        int r = warp * 8 + rr;
        const float* row = Sb + (size_t)r * 512;
        float v[16];
        float m = -1e30f;
#pragma unroll
        for (int i = 0; i < 4; i++) {
            float4 x = *reinterpret_cast<const float4*>(row + i * 128 + lane * 4);
            v[i * 4 + 0] = (mbits >> (i * 4 + 0)) & 1 ? -1e30f : x.x;
            v[i * 4 + 1] = (mbits >> (i * 4 + 1)) & 1 ? -1e30f : x.y;
            v[i * 4 + 2] = (mbits >> (i * 4 + 2)) & 1 ? -1e30f : x.z;
            v[i * 4 + 3] = (mbits >> (i * 4 + 3)) & 1 ? -1e30f : x.w;
            m = fmaxf(m, fmaxf(fmaxf(v[i * 4], v[i * 4 + 1]), fmaxf(v[i * 4 + 2], v[i * 4 + 3])));
        }
#pragma unroll
        for (int o = 16; o; o >>= 1) m = fmaxf(m, __shfl_xor_sync(0xffffffffu, m, o));
        float sum = 0.0f;
#pragma unroll
        for (int i = 0; i < 16; i++) { v[i] = __expf(v[i] - m); sum += v[i]; }
#pragma unroll
        for (int o = 16; o; o >>= 1) sum += __shfl_xor_sync(0xffffffffu, sum, o);
        float inv = 1.0f / sum;
#pragma unroll
        for (int i = 0; i < 4; i++) {
            __half2 p0 = hi2(v[i * 4 + 0] * inv, v[i * 4 + 1] * inv);
            __half2 p1 = hi2(v[i * 4 + 2] * inv, v[i * 4 + 3] * inv);
            *reinterpret_cast<uint2*>(&S->P[r][i * 128 + lane * 4]) = make_uint2(h2u(p0), h2u(p1));
        }
    }

    do_store(0);
    __syncthreads();
    do_loads(1);

    const uint32_t p_b = saddr(&S->P[0][0]);

    for (int itr = 0; itr < 16; itr++) {
        const int cur = itr & 1;
        if (itr < 15) do_store(cur ^ 1);
        if (itr < 14) do_loads(itr + 2);

        const uint32_t eh_b = saddr(&S->Eh[cur][0][0]);
        const uint32_t el_b = saddr(&S->El[cur][0][0]);

#pragma unroll
        for (int s = 0; s < 2; s++) {
            const int kb = s * 16;
            uint32_t bh[2][4], bl[2][4];
#pragma unroll
            for (int jp = 0; jp < 2; jp++) {
                uint32_t off = (uint32_t)(((kb + bt_r) * ESTR + wn + jp * 16 + bt_c) << 1);
                ldsm4t(bh[jp][0], bh[jp][1], bh[jp][2], bh[jp][3], eh_b + off);
                ldsm4t(bl[jp][0], bl[jp][1], bl[jp][2], bl[jp][3], el_b + off);
            }
#pragma unroll
            for (int i = 0; i < 2; i++) {
                uint32_t off = (uint32_t)(((wm + i * 16 + a_r) * PSTR + itr * 32 + kb + a_c) << 1);
                uint32_t ap[4];
                ldsm4(ap[0], ap[1], ap[2], ap[3], p_b + off);
#pragma unroll
                for (int j = 0; j < 4; j++) {
                    uint32_t bhf2[2] = {bh[j >> 1][(j & 1) << 1], bh[j >> 1][((j & 1) << 1) + 1]};
                    uint32_t blf2[2] = {bl[j >> 1][(j & 1) << 1], bl[j >> 1][((j & 1) << 1) + 1]};
                    mma_f16(acc[i][j], ap, bhf2);
                    mma_f16(acc[i][j], ap, blf2);
                }
            }
        }
        __syncthreads();
    }

#pragma unroll
    for (int i = 0; i < 2; i++) {
        int r0 = wm + i * 16 + g;
#pragma unroll
        for (int j = 0; j < 4; j++) {
            int n0 = wn + j * 8 + (tg << 1);
            *reinterpret_cast<float2*>(Cb + (size_t)r0 * 512 + n0) =
                make_float2(acc[i][j][0], acc[i][j][1]);
            *reinterpret_cast<float2*>(Cb + (size_t)(r0 + 8) * 512 + n0) =
                make_float2(acc[i][j][2], acc[i][j][3]);
        }
    }
}

extern "C" void kernel_launch(void* const* d_in, const int* in_sizes, int n_in,
                              void* d_out, int out_size) {
    const float* enc = nullptr;
    const float* dec = nullptr;
    const float* W = nullptr;
    const int* mask = nullptr;
    for (int i = 0; i < n_in; i++) {
        int n = in_sizes[i];
        if (n == NBATCH * NSRC * NDIM)        enc  = (const float*)d_in[i];
        else if (n == NBATCH * NPRED * NDIM)  dec  = (const float*)d_in[i];
        else if (n == NDIM * NDIM)            W    = (const float*)d_in[i];
        else if (n == NBATCH * NSRC)          mask = (const int*)d_in[i];
    }
    float* out = (float*)d_out;

    cudaFuncSetAttribute(k_context, cudaFuncAttributeMaxDynamicSharedMemorySize, SMEM_CTX_BYTES);

    k_cvt_w<<<64, 256>>>(W);
    dim3 g(4, 1, NBATCH);
    k_query<<<g, 128>>>(dec);
    k_scores<<<g, 128>>>(enc);
    k_context<<<dim3(4, 2, NBATCH), 256, SMEM_CTX_BYTES>>>(enc, mask, out);
}

// round 16
// speedup vs baseline: 1.4018x; 1.1028x over previous
#include <cuda_runtime.h>
#include <cuda_fp16.h>
#include <cstdint>

#define NBATCH 256
#define NSRC   512
#define NPRED  128
#define NDIM   512

static __device__ __align__(128) float g_Q[(size_t)NBATCH * NPRED * NDIM];  // 67 MB
static __device__ __align__(128) float g_S[(size_t)NBATCH * NPRED * NSRC];  // 67 MB

// ---------------- helpers ----------------
__device__ __forceinline__ uint32_t saddr(const void* p) {
    return (uint32_t)__cvta_generic_to_shared(p);
}
__device__ __forceinline__ __half2 hi2(float a, float b) {
    return __halves2half2(__float2half_rn(a), __float2half_rn(b));
}
__device__ __forceinline__ __half2 lo2(float a, float b, __half2 h) {
    return __halves2half2(__float2half_rn(a - __half2float(__low2half(h))),
                          __float2half_rn(b - __half2float(__high2half(h))));
}
__device__ __forceinline__ uint32_t h2u(__half2 h) {
    return *reinterpret_cast<uint32_t*>(&h);
}
__device__ __forceinline__ void mma_f16(float (&d)[4], const uint32_t* a, const uint32_t* b) {
    asm volatile(
        "mma.sync.aligned.m16n8k16.row.col.f32.f16.f16.f32 "
        "{%0,%1,%2,%3}, {%4,%5,%6,%7}, {%8,%9}, {%0,%1,%2,%3};\n"
        : "+f"(d[0]), "+f"(d[1]), "+f"(d[2]), "+f"(d[3])
        : "r"(a[0]), "r"(a[1]), "r"(a[2]), "r"(a[3]), "r"(b[0]), "r"(b[1]));
}
__device__ __forceinline__ void ldsm4(uint32_t& r0, uint32_t& r1, uint32_t& r2, uint32_t& r3,
                                      uint32_t a) {
    asm volatile("ldmatrix.sync.aligned.m8n8.x4.shared.b16 {%0,%1,%2,%3}, [%4];"
                 : "=r"(r0), "=r"(r1), "=r"(r2), "=r"(r3) : "r"(a));
}
__device__ __forceinline__ void ldsm4t(uint32_t& r0, uint32_t& r1, uint32_t& r2, uint32_t& r3,
                                       uint32_t a) {
    asm volatile("ldmatrix.sync.aligned.m8n8.x4.trans.shared.b16 {%0,%1,%2,%3}, [%4];"
                 : "=r"(r0), "=r"(r1), "=r"(r2), "=r"(r3) : "r"(a));
}

// ============================================================================
// fp16 hi/lo 3-term split GEMM-NT (R13 verbatim — measured 508us config):
// C(128x128 tile) = A(128x512) * B^T. 4 warps (2x2 grid), 64x64 warp tiles,
// BK=16, staged global loads (4 lanes/row -> 64B-contiguous LDG), ldmatrix.
// ============================================================================
#define KPAD 24  // halves per row; word = 12*row + c -> rows 0..7 hit distinct banks

__device__ __forceinline__ void split_gemm_nt(const float* __restrict__ Ab,
                                              const float* __restrict__ Bp,
                                              float* __restrict__ Cp) {
    __shared__ __half Ah[128][KPAD], Al[128][KPAD];
    __shared__ __half Bh[128][KPAD], Bl[128][KPAD];

    const int tid  = threadIdx.x;        // 0..127
    const int lane = tid & 31;
    const int warp = tid >> 5;           // 0..3
    const int wm = (warp >> 1) << 6;     // 0 or 64
    const int wn = (warp & 1) << 6;      // 0 or 64
    const int g  = lane >> 2;
    const int tg = lane & 3;

    const int a_r = lane & 15;
    const int a_c = (lane >> 4) << 3;
    const int b_r = (lane & 7) + ((lane & 16) >> 1);
    const int b_c = lane & 8;

    const uint32_t ah_b = saddr(&Ah[0][0]);
    const uint32_t al_b = saddr(&Al[0][0]);
    const uint32_t bh_b = saddr(&Bh[0][0]);
    const uint32_t bl_b = saddr(&Bl[0][0]);

    const int grow = tid >> 2;           // 0..31
    const int gcol = (tid & 3) << 2;     // 0,4,8,12

    float acc[4][8][4];
#pragma unroll
    for (int i = 0; i < 4; i++)
#pragma unroll
        for (int j = 0; j < 8; j++)
#pragma unroll
            for (int r = 0; r < 4; r++) acc[i][j][r] = 0.0f;

    float4 sa[4], sb[4];

    auto lds_g = [&](int k0) {
#pragma unroll
        for (int i = 0; i < 4; i++) {
            int row = grow + 32 * i;
            sa[i] = *reinterpret_cast<const float4*>(Ab + (size_t)row * 512 + k0 + gcol);
            sb[i] = *reinterpret_cast<const float4*>(Bp + (size_t)row * 512 + k0 + gcol);
        }
    };
    auto sts = [&]() {
#pragma unroll
        for (int i = 0; i < 4; i++) {
            int row = grow + 32 * i;
            {
                float4 v = sa[i];
                __half2 h0 = hi2(v.x, v.y), h1 = hi2(v.z, v.w);
                *reinterpret_cast<uint2*>(&Ah[row][gcol]) = make_uint2(h2u(h0), h2u(h1));
                *reinterpret_cast<uint2*>(&Al[row][gcol]) =
                    make_uint2(h2u(lo2(v.x, v.y, h0)), h2u(lo2(v.z, v.w, h1)));
            }
            {
                float4 v = sb[i];
                __half2 h0 = hi2(v.x, v.y), h1 = hi2(v.z, v.w);
                *reinterpret_cast<uint2*>(&Bh[row][gcol]) = make_uint2(h2u(h0), h2u(h1));
                *reinterpret_cast<uint2*>(&Bl[row][gcol]) =
                    make_uint2(h2u(lo2(v.x, v.y, h0)), h2u(lo2(v.z, v.w, h1)));
            }
        }
    };

    lds_g(0);
    sts();
    __syncthreads();

    for (int itr = 0; itr < 32; itr++) {
        if (itr < 31) lds_g((itr + 1) * 16);  // overlaps compute below

        uint32_t bhf[4][4], blf[4][4];
#pragma unroll
        for (int jp = 0; jp < 4; jp++) {
            uint32_t off = (uint32_t)(((wn + jp * 16 + b_r) * KPAD + b_c) << 1);
            ldsm4(bhf[jp][0], bhf[jp][1], bhf[jp][2], bhf[jp][3], bh_b + off);
            ldsm4(blf[jp][0], blf[jp][1], blf[jp][2], blf[jp][3], bl_b + off);
        }
#pragma unroll
        for (int i = 0; i < 4; i++) {
            uint32_t off = (uint32_t)(((wm + i * 16 + a_r) * KPAD + a_c) << 1);
            uint32_t ah[4], al[4];
            ldsm4(ah[0], ah[1], ah[2], ah[3], ah_b + off);
            ldsm4(al[0], al[1], al[2], al[3], al_b + off);
#pragma unroll
            for (int j = 0; j < 8; j++) {
                uint32_t b2h[2] = {bhf[j >> 1][(j & 1) << 1], bhf[j >> 1][((j & 1) << 1) + 1]};
                uint32_t b2l[2] = {blf[j >> 1][(j & 1) << 1], blf[j >> 1][((j & 1) << 1) + 1]};
                mma_f16(acc[i][j], ah, b2h);
                mma_f16(acc[i][j], ah, b2l);
                mma_f16(acc[i][j], al, b2h);
            }
        }
        __syncthreads();
        if (itr < 31) {
            sts();
            __syncthreads();
        }
    }

#pragma unroll
    for (int i = 0; i < 4; i++) {
        int r0 = wm + i * 16 + g;
#pragma unroll
        for (int j = 0; j < 8; j++) {
            int n0 = wn + j * 8 + (tg << 1);
            *reinterpret_cast<float2*>(Cp + (size_t)r0 * 512 + n0) =
                make_float2(acc[i][j][0], acc[i][j][1]);
            *reinterpret_cast<float2*>(Cp + (size_t)(r0 + 8) * 512 + n0) =
                make_float2(acc[i][j][2], acc[i][j][3]);
        }
    }
}

__global__ __launch_bounds__(128, 2) void k_query(const float* __restrict__ dec,
                                                  const float* __restrict__ W) {
    size_t b = blockIdx.z;
    split_gemm_nt(dec + b * NPRED * NDIM,
                  W + (size_t)blockIdx.x * 128 * 512,
                  g_Q + b * NPRED * NDIM + blockIdx.x * 128);
}

__global__ __launch_bounds__(128, 2) void k_scores(const float* __restrict__ enc) {
    size_t b = blockIdx.z;
    split_gemm_nt(g_Q + b * NPRED * NDIM,
                  enc + b * NSRC * NDIM + (size_t)blockIdx.x * 128 * 512,
                  g_S + b * NPRED * NSRC + blockIdx.x * 128);
}

// ============================================================================
// Fused masked-softmax + context — SINGLE-term E (fp16 hi only).
// Precision precedent: R6's single-pass TF32 context (same 11-bit mantissa)
// measured rel_err=2.46e-4 total, 4x inside the 1e-3 gate.
// Halves mainloop mma + ldsm4t, deletes all lo2 cvt chains from the E path.
// ============================================================================
#define PSTR 520
#define ESTR 136

struct SmemCtx {
    __half P[64][PSTR];        // 66,560 B
    __half Eh[2][32][ESTR];    // 17,408 B
};
#define SMEM_CTX_BYTES ((int)sizeof(SmemCtx))  // 83,968

__global__ __launch_bounds__(256, 2) void k_context(const float* __restrict__ enc,
                                                    const int* __restrict__ mask,
                                                    float* __restrict__ out) {
    extern __shared__ char smem_raw[];
    SmemCtx* S = reinterpret_cast<SmemCtx*>(smem_raw);

    const size_t b = blockIdx.z;
    const int mhalf = blockIdx.y;
    const float* Sb = g_S + ((size_t)b * 128 + mhalf * 64) * 512;
    const float* Bb = enc + b * (size_t)NSRC * NDIM + blockIdx.x * 128;
    float* Cb = out + ((size_t)b * 128 + mhalf * 64) * 512 + blockIdx.x * 128;
    const int* mrow = mask + b * (size_t)NSRC;

    const int tid  = threadIdx.x;
    const int lane = tid & 31;
    const int warp = tid >> 5;
    const int wm = (warp >> 2) << 5;   // 0 or 32
    const int wn = (warp & 3) << 5;    // 0,32,64,96
    const int g  = lane >> 2;
    const int tg = lane & 3;

    const int a_r = lane & 15;
    const int a_c = (lane >> 4) << 3;
    const int bt_r = (lane & 7) + (lane & 8);
    const int bt_c = (lane >> 4) << 3;

    const int brow = tid >> 3;         // 0..31
    const int bn0  = (tid & 7) << 4;   // 0..112

    float acc[2][4][4];
#pragma unroll
    for (int i = 0; i < 2; i++)
#pragma unroll
        for (int j = 0; j < 4; j++)
#pragma unroll
            for (int r = 0; r < 4; r++) acc[i][j][r] = 0.0f;

    float4 sbv[4];
    auto do_loads = [&](int t) {
        int k0 = t * 32;
#pragma unroll
        for (int it = 0; it < 4; it++)
            sbv[it] = *reinterpret_cast<const float4*>(Bb + (size_t)(k0 + brow) * 512 + bn0 + it * 4);
    };
    auto do_store = [&](int bf) {
#pragma unroll
        for (int u = 0; u < 2; u++) {
            int nn = bn0 + u * 8;
            float4 v0 = sbv[2 * u], v1 = sbv[2 * u + 1];
            *reinterpret_cast<uint4*>(&S->Eh[bf][brow][nn]) =
                make_uint4(h2u(hi2(v0.x, v0.y)), h2u(hi2(v0.z, v0.w)),
                           h2u(hi2(v1.x, v1.y)), h2u(hi2(v1.z, v1.w)));
        }
    };

    do_loads(0);  // enc tile 0 LDGs fly during softmax prologue

    // ---- masked softmax prologue: 8 rows per warp -> resident fp16 P ----
    uint32_t mbits = 0;
#pragma unroll
    for (int i = 0; i < 4; i++) {
        int4 mk = *reinterpret_cast<const int4*>(mrow + i * 128 + lane * 4);
        mbits |= (uint32_t)((mk.x ? 1 : 0) | (mk.y ? 2 : 0) | (mk.z ? 4 : 0) | (mk.w ? 8 : 0))
                 << (i * 4);
    }
    for (int rr = 0; rr < 8; rr++) {
        int r = warp * 8 + rr;
        const float* row = Sb + (size_t)r * 512;
        float v[16];
        float m = -1e30f;
#pragma unroll
        for (int i = 0; i < 4; i++) {
            float4 x = *reinterpret_cast<const float4*>(row + i * 128 + lane * 4);
            v[i * 4 + 0] = (mbits >> (i * 4 + 0)) & 1 ? -1e30f : x.x;
            v[i * 4 + 1] = (mbits >> (i * 4 + 1)) & 1 ? -1e30f : x.y;
            v[i * 4 + 2] = (mbits >> (i * 4 + 2)) & 1 ? -1e30f : x.z;
            v[i * 4 + 3] = (mbits >> (i * 4 + 3)) & 1 ? -1e30f : x.w;
            m = fmaxf(m, fmaxf(fmaxf(v[i * 4], v[i * 4 + 1]), fmaxf(v[i * 4 + 2], v[i * 4 + 3])));
        }
#pragma unroll
        for (int o = 16; o; o >>= 1) m = fmaxf(m, __shfl_xor_sync(0xffffffffu, m, o));
        float sum = 0.0f;
#pragma unroll
        for (int i = 0; i < 16; i++) { v[i] = __expf(v[i] - m); sum += v[i]; }
#pragma unroll
        for (int o = 16; o; o >>= 1) sum += __shfl_xor_sync(0xffffffffu, sum, o);
        float inv = 1.0f / sum;
#pragma unroll
        for (int i = 0; i < 4; i++) {
            __half2 p0 = hi2(v[i * 4 + 0] * inv, v[i * 4 + 1] * inv);
            __half2 p1 = hi2(v[i * 4 + 2] * inv, v[i * 4 + 3] * inv);
            *reinterpret_cast<uint2*>(&S->P[r][i * 128 + lane * 4]) = make_uint2(h2u(p0), h2u(p1));
        }
    }

    do_store(0);
    __syncthreads();
    do_loads(1);

    const uint32_t p_b = saddr(&S->P[0][0]);

    for (int itr = 0; itr < 16; itr++) {
        const int cur = itr & 1;
        if (itr < 15) do_store(cur ^ 1);
        if (itr < 14) do_loads(itr + 2);

        const uint32_t eh_b = saddr(&S->Eh[cur][0][0]);

#pragma unroll
        for (int s = 0; s < 2; s++) {
            const int kb = s * 16;
            uint32_t bh[2][4];
#pragma unroll
            for (int jp = 0; jp < 2; jp++) {
                uint32_t off = (uint32_t)(((kb + bt_r) * ESTR + wn + jp * 16 + bt_c) << 1);
                ldsm4t(bh[jp][0], bh[jp][1], bh[jp][2], bh[jp][3], eh_b + off);
            }
#pragma unroll
            for (int i = 0; i < 2; i++) {
                uint32_t off = (uint32_t)(((wm + i * 16 + a_r) * PSTR + itr * 32 + kb + a_c) << 1);
                uint32_t ap[4];
                ldsm4(ap[0], ap[1], ap[2], ap[3], p_b + off);
#pragma unroll
                for (int j = 0; j < 4; j++) {
                    uint32_t b2h[2] = {bh[j >> 1][(j & 1) << 1], bh[j >> 1][((j & 1) << 1) + 1]};
                    mma_f16(acc[i][j], ap, b2h);
                }
            }
        }
        __syncthreads();
    }

#pragma unroll
    for (int i = 0; i < 2; i++) {
        int r0 = wm + i * 16 + g;
#pragma unroll
        for (int j = 0; j < 4; j++) {
            int n0 = wn + j * 8 + (tg << 1);
            *reinterpret_cast<float2*>(Cb + (size_t)r0 * 512 + n0) =
                make_float2(acc[i][j][0], acc[i][j][1]);
            *reinterpret_cast<float2*>(Cb + (size_t)(r0 + 8) * 512 + n0) =
                make_float2(acc[i][j][2], acc[i][j][3]);
        }
    }
}

extern "C" void kernel_launch(void* const* d_in, const int* in_sizes, int n_in,
                              void* d_out, int out_size) {
    const float* enc = nullptr;
    const float* dec = nullptr;
    const float* W = nullptr;
    const int* mask = nullptr;
    for (int i = 0; i < n_in; i++) {
        int n = in_sizes[i];
        if (n == NBATCH * NSRC * NDIM)        enc  = (const float*)d_in[i];
        else if (n == NBATCH * NPRED * NDIM)  dec  = (const float*)d_in[i];
        else if (n == NDIM * NDIM)            W    = (const float*)d_in[i];
        else if (n == NBATCH * NSRC)          mask = (const int*)d_in[i];
    }
    float* out = (float*)d_out;

    cudaFuncSetAttribute(k_context, cudaFuncAttributeMaxDynamicSharedMemorySize, SMEM_CTX_BYTES);

    dim3 g(4, 1, NBATCH);
    k_query<<<g, 128>>>(dec, W);
    k_scores<<<g, 128>>>(enc);
    k_context<<<dim3(4, 2, NBATCH), 256, SMEM_CTX_BYTES>>>(enc, mask, out);
}

// round 17
// speedup vs baseline: 1.4183x; 1.0118x over previous
#include <cuda_runtime.h>
#include <cuda_fp16.h>
#include <cstdint>

#define NBATCH 256
#define NSRC   512
#define NPRED  128
#define NDIM   512

static __device__ __align__(128) float g_Q[(size_t)NBATCH * NPRED * NDIM];  // 67 MB
static __device__ __align__(128) float g_S[(size_t)NBATCH * NPRED * NSRC];  // 67 MB

// ---------------- helpers ----------------
__device__ __forceinline__ uint32_t saddr(const void* p) {
    return (uint32_t)__cvta_generic_to_shared(p);
}
__device__ __forceinline__ __half2 hi2(float a, float b) {
    return __halves2half2(__float2half_rn(a), __float2half_rn(b));
}
__device__ __forceinline__ __half2 lo2(float a, float b, __half2 h) {
    return __halves2half2(__float2half_rn(a - __half2float(__low2half(h))),
                          __float2half_rn(b - __half2float(__high2half(h))));
}
__device__ __forceinline__ uint32_t h2u(__half2 h) {
    return *reinterpret_cast<uint32_t*>(&h);
}
__device__ __forceinline__ void mma_f16(float (&d)[4], const uint32_t* a, const uint32_t* b) {
    asm volatile(
        "mma.sync.aligned.m16n8k16.row.col.f32.f16.f16.f32 "
        "{%0,%1,%2,%3}, {%4,%5,%6,%7}, {%8,%9}, {%0,%1,%2,%3};\n"
        : "+f"(d[0]), "+f"(d[1]), "+f"(d[2]), "+f"(d[3])
        : "r"(a[0]), "r"(a[1]), "r"(a[2]), "r"(a[3]), "r"(b[0]), "r"(b[1]));
}
__device__ __forceinline__ void ldsm4(uint32_t& r0, uint32_t& r1, uint32_t& r2, uint32_t& r3,
                                      uint32_t a) {
    asm volatile("ldmatrix.sync.aligned.m8n8.x4.shared.b16 {%0,%1,%2,%3}, [%4];"
                 : "=r"(r0), "=r"(r1), "=r"(r2), "=r"(r3) : "r"(a));
}
__device__ __forceinline__ void ldsm4t(uint32_t& r0, uint32_t& r1, uint32_t& r2, uint32_t& r3,
                                       uint32_t a) {
    asm volatile("ldmatrix.sync.aligned.m8n8.x4.trans.shared.b16 {%0,%1,%2,%3}, [%4];"
                 : "=r"(r0), "=r"(r1), "=r"(r2), "=r"(r3) : "r"(a));
}

// ============================================================================
// fp16 hi/lo 3-term split GEMM-NT: C(128x128 tile) = A(128x512) * B^T.
// R13/R16 structure (4 warps, 2x2 grid, 64x64 warp tiles, BK=16, KPAD=24)
// + DOUBLE-BUFFERED smem with ONE __syncthreads per k-iter:
//   sts(next chunk -> other buffer) ; lds_g(chunk+2) ; compute(cur) ; sync
// ============================================================================
#define KPAD 24  // halves per row; word = 12*row + c -> 8-row LDSM groups conflict-free

__device__ __forceinline__ void split_gemm_nt(const float* __restrict__ Ab,
                                              const float* __restrict__ Bp,
                                              float* __restrict__ Cp) {
    __shared__ __half Ah[2][128][KPAD], Al[2][128][KPAD];
    __shared__ __half Bh[2][128][KPAD], Bl[2][128][KPAD];   // 49,152 B total

    const int tid  = threadIdx.x;        // 0..127
    const int lane = tid & 31;
    const int warp = tid >> 5;           // 0..3
    const int wm = (warp >> 1) << 6;     // 0 or 64
    const int wn = (warp & 1) << 6;      // 0 or 64
    const int g  = lane >> 2;
    const int tg = lane & 3;

    const int a_r = lane & 15;
    const int a_c = (lane >> 4) << 3;
    const int b_r = (lane & 7) + ((lane & 16) >> 1);
    const int b_c = lane & 8;

    const int grow = tid >> 2;           // 0..31
    const int gcol = (tid & 3) << 2;     // 0,4,8,12

    float acc[4][8][4];
#pragma unroll
    for (int i = 0; i < 4; i++)
#pragma unroll
        for (int j = 0; j < 8; j++)
#pragma unroll
            for (int r = 0; r < 4; r++) acc[i][j][r] = 0.0f;

    float4 sa[4], sb[4];

    auto lds_g = [&](int k0) {
#pragma unroll
        for (int i = 0; i < 4; i++) {
            int row = grow + 32 * i;
            sa[i] = *reinterpret_cast<const float4*>(Ab + (size_t)row * 512 + k0 + gcol);
            sb[i] = *reinterpret_cast<const float4*>(Bp + (size_t)row * 512 + k0 + gcol);
        }
    };
    auto sts = [&](int bf) {
#pragma unroll
        for (int i = 0; i < 4; i++) {
            int row = grow + 32 * i;
            {
                float4 v = sa[i];
                __half2 h0 = hi2(v.x, v.y), h1 = hi2(v.z, v.w);
                *reinterpret_cast<uint2*>(&Ah[bf][row][gcol]) = make_uint2(h2u(h0), h2u(h1));
                *reinterpret_cast<uint2*>(&Al[bf][row][gcol]) =
                    make_uint2(h2u(lo2(v.x, v.y, h0)), h2u(lo2(v.z, v.w, h1)));
            }
            {
                float4 v = sb[i];
                __half2 h0 = hi2(v.x, v.y), h1 = hi2(v.z, v.w);
                *reinterpret_cast<uint2*>(&Bh[bf][row][gcol]) = make_uint2(h2u(h0), h2u(h1));
                *reinterpret_cast<uint2*>(&Bl[bf][row][gcol]) =
                    make_uint2(h2u(lo2(v.x, v.y, h0)), h2u(lo2(v.z, v.w, h1)));
            }
        }
    };

    lds_g(0);
    sts(0);
    __syncthreads();
    lds_g(16);

    for (int itr = 0; itr < 32; itr++) {
        const int cur = itr & 1;
        // stage chunk itr+1 into the other buffer (its last reader finished at
        // the barrier ending iter itr-1), then start LDGs for chunk itr+2.
        if (itr < 31) sts(cur ^ 1);
        if (itr < 30) lds_g((itr + 2) * 16);

        const uint32_t ah_b = saddr(&Ah[cur][0][0]);
        const uint32_t al_b = saddr(&Al[cur][0][0]);
        const uint32_t bh_b = saddr(&Bh[cur][0][0]);
        const uint32_t bl_b = saddr(&Bl[cur][0][0]);

        uint32_t bhf[4][4], blf[4][4];
#pragma unroll
        for (int jp = 0; jp < 4; jp++) {
            uint32_t off = (uint32_t)(((wn + jp * 16 + b_r) * KPAD + b_c) << 1);
            ldsm4(bhf[jp][0], bhf[jp][1], bhf[jp][2], bhf[jp][3], bh_b + off);
            ldsm4(blf[jp][0], blf[jp][1], blf[jp][2], blf[jp][3], bl_b + off);
        }
#pragma unroll
        for (int i = 0; i < 4; i++) {
            uint32_t off = (uint32_t)(((wm + i * 16 + a_r) * KPAD + a_c) << 1);
            uint32_t ah[4], al[4];
            ldsm4(ah[0], ah[1], ah[2], ah[3], ah_b + off);
            ldsm4(al[0], al[1], al[2], al[3], al_b + off);
#pragma unroll
            for (int j = 0; j < 8; j++) {
                uint32_t b2h[2] = {bhf[j >> 1][(j & 1) << 1], bhf[j >> 1][((j & 1) << 1) + 1]};
                uint32_t b2l[2] = {blf[j >> 1][(j & 1) << 1], blf[j >> 1][((j & 1) << 1) + 1]};
                mma_f16(acc[i][j], ah, b2h);
                mma_f16(acc[i][j], ah, b2l);
                mma_f16(acc[i][j], al, b2h);
            }
        }
        __syncthreads();   // single barrier per iter
    }

#pragma unroll
    for (int i = 0; i < 4; i++) {
        int r0 = wm + i * 16 + g;
#pragma unroll
        for (int j = 0; j < 8; j++) {
            int n0 = wn + j * 8 + (tg << 1);
            *reinterpret_cast<float2*>(Cp + (size_t)r0 * 512 + n0) =
                make_float2(acc[i][j][0], acc[i][j][1]);
            *reinterpret_cast<float2*>(Cp + (size_t)(r0 + 8) * 512 + n0) =
                make_float2(acc[i][j][2], acc[i][j][3]);
        }
    }
}

__global__ __launch_bounds__(128, 2) void k_query(const float* __restrict__ dec,
                                                  const float* __restrict__ W) {
    size_t b = blockIdx.z;
    split_gemm_nt(dec + b * NPRED * NDIM,
                  W + (size_t)blockIdx.x * 128 * 512,
                  g_Q + b * NPRED * NDIM + blockIdx.x * 128);
}

__global__ __launch_bounds__(128, 2) void k_scores(const float* __restrict__ enc) {
    size_t b = blockIdx.z;
    split_gemm_nt(g_Q + b * NPRED * NDIM,
                  enc + b * NSRC * NDIM + (size_t)blockIdx.x * 128 * 512,
                  g_S + b * NPRED * NSRC + blockIdx.x * 128);
}

// ============================================================================
// Fused masked-softmax + context — single-term E (R16 verbatim, measured
// rel_err 2.458e-4 total with this config).
// ============================================================================
#define PSTR 520
#define ESTR 136

struct SmemCtx {
    __half P[64][PSTR];        // 66,560 B
    __half Eh[2][32][ESTR];    // 17,408 B
};
#define SMEM_CTX_BYTES ((int)sizeof(SmemCtx))  // 83,968

__global__ __launch_bounds__(256, 2) void k_context(const float* __restrict__ enc,
                                                    const int* __restrict__ mask,
                                                    float* __restrict__ out) {
    extern __shared__ char smem_raw[];
    SmemCtx* S = reinterpret_cast<SmemCtx*>(smem_raw);

    const size_t b = blockIdx.z;
    const int mhalf = blockIdx.y;
    const float* Sb = g_S + ((size_t)b * 128 + mhalf * 64) * 512;
    const float* Bb = enc + b * (size_t)NSRC * NDIM + blockIdx.x * 128;
    float* Cb = out + ((size_t)b * 128 + mhalf * 64) * 512 + blockIdx.x * 128;
    const int* mrow = mask + b * (size_t)NSRC;

    const int tid  = threadIdx.x;
    const int lane = tid & 31;
    const int warp = tid >> 5;
    const int wm = (warp >> 2) << 5;   // 0 or 32
    const int wn = (warp & 3) << 5;    // 0,32,64,96
    const int g  = lane >> 2;
    const int tg = lane & 3;

    const int a_r = lane & 15;
    const int a_c = (lane >> 4) << 3;
    const int bt_r = (lane & 7) + (lane & 8);
    const int bt_c = (lane >> 4) << 3;

    const int brow = tid >> 3;         // 0..31
    const int bn0  = (tid & 7) << 4;   // 0..112

    float acc[2][4][4];
#pragma unroll
    for (int i = 0; i < 2; i++)
#pragma unroll
        for (int j = 0; j < 4; j++)
#pragma unroll
            for (int r = 0; r < 4; r++) acc[i][j][r] = 0.0f;

    float4 sbv[4];
    auto do_loads = [&](int t) {
        int k0 = t * 32;
#pragma unroll
        for (int it = 0; it < 4; it++)
            sbv[it] = *reinterpret_cast<const float4*>(Bb + (size_t)(k0 + brow) * 512 + bn0 + it * 4);
    };
    auto do_store = [&](int bf) {
#pragma unroll
        for (int u = 0; u < 2; u++) {
            int nn = bn0 + u * 8;
            float4 v0 = sbv[2 * u], v1 = sbv[2 * u + 1];
            *reinterpret_cast<uint4*>(&S->Eh[bf][brow][nn]) =
                make_uint4(h2u(hi2(v0.x, v0.y)), h2u(hi2(v0.z, v0.w)),
                           h2u(hi2(v1.x, v1.y)), h2u(hi2(v1.z, v1.w)));
        }
    };

    do_loads(0);  // enc tile 0 LDGs fly during softmax prologue

    // ---- masked softmax prologue: 8 rows per warp -> resident fp16 P ----
    uint32_t mbits = 0;
#pragma unroll
    for (int i = 0; i < 4; i++) {
        int4 mk = *reinterpret_cast<const int4*>(mrow + i * 128 + lane * 4);
        mbits |= (uint32_t)((mk.x ? 1 : 0) | (mk.y ? 2 : 0) | (mk.z ? 4 : 0) | (mk.w ? 8 : 0))
                 << (i * 4);
    }
    for (int rr = 0; rr < 8; rr++) {
        int r = warp * 8 + rr;
        const float* row = Sb + (size_t)r * 512;
        float v[16];
        float m = -1e30f;
#pragma unroll
        for (int i = 0; i < 4; i++) {
            float4 x = *reinterpret_cast<const float4*>(row + i * 128 + lane * 4);
            v[i * 4 + 0] = (mbits >> (i * 4 + 0)) & 1 ? -1e30f : x.x;
            v[i * 4 + 1] = (mbits >> (i * 4 + 1)) & 1 ? -1e30f : x.y;
            v[i * 4 + 2] = (mbits >> (i * 4 + 2)) & 1 ? -1e30f : x.z;
            v[i * 4 + 3] = (mbits >> (i * 4 + 3)) & 1 ? -1e30f : x.w;
            m = fmaxf(m, fmaxf(fmaxf(v[i * 4], v[i * 4 + 1]), fmaxf(v[i * 4 + 2], v[i * 4 + 3])));
        }
#pragma unroll
        for (int o = 16; o; o >>= 1) m = fmaxf(m, __shfl_xor_sync(0xffffffffu, m, o));
        float sum = 0.0f;
#pragma unroll
        for (int i = 0; i < 16; i++) { v[i] = __expf(v[i] - m); sum += v[i]; }
#pragma unroll
        for (int o = 16; o; o >>= 1) sum += __shfl_xor_sync(0xffffffffu, sum, o);
        float inv = 1.0f / sum;
#pragma unroll
        for (int i = 0; i < 4; i++) {
            __half2 p0 = hi2(v[i * 4 + 0] * inv, v[i * 4 + 1] * inv);
            __half2 p1 = hi2(v[i * 4 + 2] * inv, v[i * 4 + 3] * inv);
            *reinterpret_cast<uint2*>(&S->P[r][i * 128 + lane * 4]) = make_uint2(h2u(p0), h2u(p1));
        }
    }

    do_store(0);
    __syncthreads();
    do_loads(1);

    const uint32_t p_b = saddr(&S->P[0][0]);

    for (int itr = 0; itr < 16; itr++) {
        const int cur = itr & 1;
        if (itr < 15) do_store(cur ^ 1);
        if (itr < 14) do_loads(itr + 2);

        const uint32_t eh_b = saddr(&S->Eh[cur][0][0]);

#pragma unroll
        for (int s = 0; s < 2; s++) {
            const int kb = s * 16;
            uint32_t bh[2][4];
#pragma unroll
            for (int jp = 0; jp < 2; jp++) {
                uint32_t off = (uint32_t)(((kb + bt_r) * ESTR + wn + jp * 16 + bt_c) << 1);
                ldsm4t(bh[jp][0], bh[jp][1], bh[jp][2], bh[jp][3], eh_b + off);
            }
#pragma unroll
            for (int i = 0; i < 2; i++) {
                uint32_t off = (uint32_t)(((wm + i * 16 + a_r) * PSTR + itr * 32 + kb + a_c) << 1);
                uint32_t ap[4];
                ldsm4(ap[0], ap[1], ap[2], ap[3], p_b + off);
#pragma unroll
                for (int j = 0; j < 4; j++) {
                    uint32_t b2h[2] = {bh[j >> 1][(j & 1) << 1], bh[j >> 1][((j & 1) << 1) + 1]};
                    mma_f16(acc[i][j], ap, b2h);
                }
            }
        }
        __syncthreads();
    }

#pragma unroll
    for (int i = 0; i < 2; i++) {
        int r0 = wm + i * 16 + g;
#pragma unroll
        for (int j = 0; j < 4; j++) {
            int n0 = wn + j * 8 + (tg << 1);
            *reinterpret_cast<float2*>(Cb + (size_t)r0 * 512 + n0) =
                make_float2(acc[i][j][0], acc[i][j][1]);
            *reinterpret_cast<float2*>(Cb + (size_t)(r0 + 8) * 512 + n0) =
                make_float2(acc[i][j][2], acc[i][j][3]);
        }
    }
}

extern "C" void kernel_launch(void* const* d_in, const int* in_sizes, int n_in,
                              void* d_out, int out_size) {
    const float* enc = nullptr;
    const float* dec = nullptr;
    const float* W = nullptr;
    const int* mask = nullptr;
    for (int i = 0; i < n_in; i++) {
        int n = in_sizes[i];
        if (n == NBATCH * NSRC * NDIM)        enc  = (const float*)d_in[i];
        else if (n == NBATCH * NPRED * NDIM)  dec  = (const float*)d_in[i];
        else if (n == NDIM * NDIM)            W    = (const float*)d_in[i];
        else if (n == NBATCH * NSRC)          mask = (const int*)d_in[i];
    }
    float* out = (float*)d_out;

    cudaFuncSetAttribute(k_context, cudaFuncAttributeMaxDynamicSharedMemorySize, SMEM_CTX_BYTES);

    dim3 g(4, 1, NBATCH);
    k_query<<<g, 128>>>(dec, W);
    k_scores<<<g, 128>>>(enc);
    k_context<<<dim3(4, 2, NBATCH), 256, SMEM_CTX_BYTES>>>(enc, mask, out);
}